// round 4
// baseline (speedup 1.0000x reference)
#include <cuda_runtime.h>
#include <cstdint>

#define NPTS 8192
#define KNN  8

// ---------------- scratch (static device globals; no allocation) ----------------
__device__ __align__(16) float4 g_pts4[NPTS];              // x,y,z,|x|^2
__device__ int                  g_idx[NPTS * KNN];         // knn indices (flat)
__device__ __align__(16) float  g_qp1[NPTS * 128];         // [i][0:64]=qA1, [64:128]=pB1
__device__ __align__(16) float  g_x1 [NPTS * 128];         // EdgeConv1 output
__device__ __align__(16) float  g_qp2[NPTS * 256];         // [i][0:128]=qA2, [128:256]=pB2
__device__ __align__(16) float  g_wcat[128 * 256];         // [W3a-W3b | W3b]

// ---------------- prep: pack points + squared norms ----------------
__global__ void k_prep(const float* __restrict__ pc) {
    int i = blockIdx.x * blockDim.x + threadIdx.x;
    if (i < NPTS) {
        float x = pc[3*i], y = pc[3*i+1], z = pc[3*i+2];
        float s = fmaf(x, x, fmaf(y, y, z*z));
        g_pts4[i] = make_float4(x, y, z, s);
    }
}

// ---------------- KNN: block = 64 points x 4 parts, all pts in smem ----------------
__global__ void k_knn() {
    extern __shared__ char sm[];
    float4* sp = (float4*)sm;                                   // 8192 float4 = 128KB
    float*  md = (float*)(sm + NPTS * 16);                      // 64*33 floats
    int*    mi = (int*)  (sm + NPTS * 16 + 64 * 33 * 4);        // 64*33 ints

    int tid = threadIdx.x;
    for (int t = tid; t < NPTS; t += 256) sp[t] = g_pts4[t];
    __syncthreads();

    int part = tid >> 6;             // warp-uniform
    int lp   = tid & 63;
    int pt   = blockIdx.x * 64 + lp;
    float4 me = sp[pt];

    float bd[8]; int bj[8];
#pragma unroll
    for (int s = 0; s < 8; s++) { bd[s] = 3.4e38f; bj[s] = 0x7fffffff; }

    int j0 = part * 2048;
#pragma unroll 4
    for (int jj = 0; jj < 2048; jj++) {
        int j = j0 + jj;
        float4 o = sp[j];
        float dot = fmaf(me.x, o.x, fmaf(me.y, o.y, me.z * o.z));
        float d   = fmaf(-2.0f, dot, me.w + o.w);
        if (d < bd[7]) {                            // strict <: earlier (lower) j wins ties
            bd[7] = d; bj[7] = j;
#pragma unroll
            for (int s = 7; s > 0; s--) {
                if (bd[s] < bd[s-1]) {
                    float td = bd[s]; bd[s] = bd[s-1]; bd[s-1] = td;
                    int   tj = bj[s]; bj[s] = bj[s-1]; bj[s-1] = tj;
                }
            }
        }
    }
#pragma unroll
    for (int s = 0; s < 8; s++) {
        md[lp * 33 + part * 8 + s] = bd[s];
        mi[lp * 33 + part * 8 + s] = bj[s];
    }
    __syncthreads();

    if (tid < 64) {                 // 4-way merge: 8 passes of lex-min over 32
        float* rd = md + tid * 33;
        int*   ri = mi + tid * 33;
        int po = (blockIdx.x * 64 + tid) * KNN;
        for (int s = 0; s < 8; s++) {
            float bdd = 3.4e38f; int bjj = 0x7fffffff; int bp = 0;
            for (int t = 0; t < 32; t++) {
                float dd = rd[t]; int jj = ri[t];
                if (dd < bdd || (dd == bdd && jj < bjj)) { bdd = dd; bjj = jj; bp = t; }
            }
            rd[bp] = 3.4e38f;
            g_idx[po + s] = bjj;
        }
    }
}

// ---------------- P1: x(8192,3) -> qA1 (x@(W1a-W1b)) | pB1 (x@W1b), 64 cols each ----------------
__global__ void k_lin1(const float* __restrict__ W1, const float* __restrict__ pc) {
    int g = blockIdx.x * blockDim.x + threadIdx.x;      // NPTS*32 tasks (float4 each)
    if (g >= NPTS * 32) return;
    int i = g >> 5, q = g & 31;
    float x0 = pc[3*i], x1 = pc[3*i+1], x2 = pc[3*i+2];
    bool isQ = (q < 16);
    int c = (isQ ? q : q - 16) * 4;
    float v[4];
#pragma unroll
    for (int u = 0; u < 4; u++) {
        float wa0 = W1[0*64 + c+u], wa1 = W1[1*64 + c+u], wa2 = W1[2*64 + c+u];
        float wb0 = W1[3*64 + c+u], wb1 = W1[4*64 + c+u], wb2 = W1[5*64 + c+u];
        if (isQ) v[u] = x0*(wa0-wb0) + x1*(wa1-wb1) + x2*(wa2-wb2);
        else     v[u] = x0*wb0 + x1*wb1 + x2*wb2;
    }
    *(float4*)&g_qp1[i * 128 + q * 4] = make_float4(v[0], v[1], v[2], v[3]);
}

// ---------------- build Wcat = [W3a - W3b | W3b]  (128 x 256) ----------------
__global__ void k_wcat(const float* __restrict__ W3) {
    int g = blockIdx.x * blockDim.x + threadIdx.x;      // 128*256
    if (g >= 128 * 256) return;
    int m = g >> 8, n = g & 255;
    float v;
    if (n < 128) v = W3[m * 128 + n] - W3[(m + 128) * 128 + n];
    else         v = W3[(m + 128) * 128 + (n - 128)];
    g_wcat[m * 256 + n] = v;
}

// ---------------- fused GEMM (+optional edge A-gen, +optional max epilogue) ----------------
// Block: 64 rows x NOUT cols, 256 threads, full-K in smem.
// EDGE:  A[r][c] = relu(qA[i][c] + pB[idx[r]][c] + bK[c]),  i = r/8; epilogue = max over 8 k-rows (+bN, opt relu)
// PLAIN: A[r][c] = qA[row][c]; epilogue stores all 64 rows, no bias.
template<int KDIM, int NOUT, int NG, bool EDGE, bool RELU_OUT>
__global__ void __launch_bounds__(256) k_gemm(
    const float* __restrict__ qA, const float* __restrict__ pB, int qstride,
    const float* __restrict__ bK, const float* __restrict__ Wg,
    const float* __restrict__ bN, float* __restrict__ out)
{
    extern __shared__ float smf[];
    float* As = smf;                  // [KDIM][64]
    float* Ws = smf + KDIM * 64;      // [KDIM][NOUT]
    int tid = threadIdx.x;
    int blk = blockIdx.x;

    // load full weight tile (row-major matches gmem layout)
    {
        const int WTOT = KDIM * NOUT / 4;
        float4*       Ws4 = (float4*)Ws;
        const float4* Wg4 = (const float4*)Wg;
        for (int t = tid; t < WTOT; t += 256) Ws4[t] = Wg4[t];
    }

    // generate A tile (transposed: As[c][rr])
    {
        const int TASKS = 64 * (KDIM / 4);
        int base64 = blk * 64;
        for (int t = tid; t < TASKS; t += 256) {
            int rr = t & 63, c4 = t >> 6;
            float4 v;
            if (EDGE) {
                int i = (base64 + rr) >> 3;
                int j = g_idx[base64 + rr];
                float4 q = *(const float4*)&qA[i * qstride + c4 * 4];
                float4 p = *(const float4*)&pB[(long)j * qstride + c4 * 4];
                float4 b = *(const float4*)&bK[c4 * 4];
                v.x = fmaxf(q.x + p.x + b.x, 0.0f);
                v.y = fmaxf(q.y + p.y + b.y, 0.0f);
                v.z = fmaxf(q.z + p.z + b.z, 0.0f);
                v.w = fmaxf(q.w + p.w + b.w, 0.0f);
            } else {
                v = *(const float4*)&qA[(base64 + rr) * qstride + c4 * 4];
            }
            As[(c4*4 + 0) * 64 + rr] = v.x;
            As[(c4*4 + 1) * 64 + rr] = v.y;
            As[(c4*4 + 2) * 64 + rr] = v.z;
            As[(c4*4 + 3) * 64 + rr] = v.w;
        }
    }
    __syncthreads();

    int tm = tid >> 5;        // warp id -> all lanes share tm => A smem loads broadcast
    int tn = tid & 31;        // lane -> consecutive float4 W loads (conflict-free)

    float acc[8][NG][4];
#pragma unroll
    for (int kk = 0; kk < 8; kk++)
#pragma unroll
        for (int g = 0; g < NG; g++)
#pragma unroll
            for (int u = 0; u < 4; u++) acc[kk][g][u] = 0.0f;

#pragma unroll 4
    for (int c = 0; c < KDIM; c++) {
        float4 a0 = *(const float4*)&As[c * 64 + tm * 8];
        float4 a1 = *(const float4*)&As[c * 64 + tm * 8 + 4];
        float a[8] = {a0.x, a0.y, a0.z, a0.w, a1.x, a1.y, a1.z, a1.w};
        float4 w0 = *(const float4*)&Ws[c * NOUT + tn * 4];
        float4 w1;
        if (NG == 2) w1 = *(const float4*)&Ws[c * NOUT + (NOUT/2) + tn * 4];
#pragma unroll
        for (int kk = 0; kk < 8; kk++) {
            acc[kk][0][0] = fmaf(a[kk], w0.x, acc[kk][0][0]);
            acc[kk][0][1] = fmaf(a[kk], w0.y, acc[kk][0][1]);
            acc[kk][0][2] = fmaf(a[kk], w0.z, acc[kk][0][2]);
            acc[kk][0][3] = fmaf(a[kk], w0.w, acc[kk][0][3]);
            if (NG == 2) {
                acc[kk][1][0] = fmaf(a[kk], w1.x, acc[kk][1][0]);
                acc[kk][1][1] = fmaf(a[kk], w1.y, acc[kk][1][1]);
                acc[kk][1][2] = fmaf(a[kk], w1.z, acc[kk][1][2]);
                acc[kk][1][3] = fmaf(a[kk], w1.w, acc[kk][1][3]);
            }
        }
    }

    if (EDGE) {
        int pt = blk * 8 + tm;        // one point per warp-row => max is register-local
#pragma unroll
        for (int g = 0; g < NG; g++) {
            float res[4];
#pragma unroll
            for (int u = 0; u < 4; u++) {
                float m = acc[0][g][u];
#pragma unroll
                for (int kk = 1; kk < 8; kk++) m = fmaxf(m, acc[kk][g][u]);
                int n = g * (NOUT/2) + tn * 4 + u;
                m += bN[n];
                if (RELU_OUT) m = fmaxf(m, 0.0f);
                res[u] = m;
            }
            int n0 = g * (NOUT/2) + tn * 4;
            *(float4*)&out[(long)pt * NOUT + n0] = make_float4(res[0], res[1], res[2], res[3]);
        }
    } else {
        int base = blk * 64;
#pragma unroll
        for (int kk = 0; kk < 8; kk++) {
            int row = base + tm * 8 + kk;
#pragma unroll
            for (int g = 0; g < NG; g++) {
                int n0 = g * (NOUT/2) + tn * 4;
                *(float4*)&out[(long)row * NOUT + n0] =
                    make_float4(acc[kk][g][0], acc[kk][g][1], acc[kk][g][2], acc[kk][g][3]);
            }
        }
    }
}

// ---------------- launch ----------------
extern "C" void kernel_launch(void* const* d_in, const int* in_sizes, int n_in,
                              void* d_out, int out_size) {
    const float* pc = (const float*)d_in[0];
    const float* W1 = (const float*)d_in[1];
    const float* b1 = (const float*)d_in[2];
    const float* W2 = (const float*)d_in[3];
    const float* b2 = (const float*)d_in[4];
    const float* W3 = (const float*)d_in[5];
    const float* b3 = (const float*)d_in[6];
    const float* W4 = (const float*)d_in[7];
    const float* b4 = (const float*)d_in[8];
    float* out = (float*)d_out;

    // CRITICAL: resolve REAL device addresses of the __device__ scratch symbols.
    // (Passing the symbol name from host code yields the host shadow, which GB300's
    // ATS happily dereferences into host memory -> silent wrong results.)
    float *qp1 = nullptr, *x1 = nullptr, *qp2 = nullptr, *wcat = nullptr;
    cudaGetSymbolAddress((void**)&qp1,  g_qp1);
    cudaGetSymbolAddress((void**)&x1,   g_x1);
    cudaGetSymbolAddress((void**)&qp2,  g_qp2);
    cudaGetSymbolAddress((void**)&wcat, g_wcat);

    const int SM_KNN = NPTS * 16 + 2 * 64 * 33 * 4;                 // 147968
    const int SM_EC1 = (64 * 64 + 64 * 128) * 4;                    // 49152
    const int SM_BIG = (128 * 64 + 128 * 256) * 4;                  // 163840

    // attribute setting: query/config APIs, not stream ops -> capture-safe; idempotent
    cudaFuncSetAttribute(k_knn, cudaFuncAttributeMaxDynamicSharedMemorySize, SM_KNN);
    cudaFuncSetAttribute((const void*)k_gemm<64,128,1,true,true>,
                         cudaFuncAttributeMaxDynamicSharedMemorySize, SM_EC1);
    cudaFuncSetAttribute((const void*)k_gemm<128,256,2,false,false>,
                         cudaFuncAttributeMaxDynamicSharedMemorySize, SM_BIG);
    cudaFuncSetAttribute((const void*)k_gemm<128,256,2,true,false>,
                         cudaFuncAttributeMaxDynamicSharedMemorySize, SM_BIG);

    // 1. pack points
    k_prep<<<(NPTS + 255) / 256, 256>>>(pc);
    // 2. knn
    k_knn<<<NPTS / 64, 256, SM_KNN>>>();
    // 3. per-point linear factors for EdgeConv1
    k_lin1<<<(NPTS * 32 + 255) / 256, 256>>>(W1, pc);
    // 4. EdgeConv1: edge GEMM (K=64 -> N=128) + max + relu  -> x1
    k_gemm<64,128,1,true,true><<<NPTS * KNN / 64, 256, SM_EC1>>>(
        qp1, qp1 + 64, 128, b1, W2, b2, x1);
    // 5. Wcat = [W3a - W3b | W3b]
    k_wcat<<<(128 * 256 + 255) / 256, 256>>>(W3);
    // 6. P2: x1 @ Wcat -> qA2|pB2
    k_gemm<128,256,2,false,false><<<NPTS / 64, 256, SM_BIG>>>(
        x1, nullptr, 128, nullptr, wcat, nullptr, qp2);
    // 7. EdgeConv2: edge GEMM (K=128 -> N=256) + max  -> out
    k_gemm<128,256,2,true,false><<<NPTS * KNN / 64, 256, SM_BIG>>>(
        qp2, qp2 + 128, 256, b3, W4, b4, out);
}

// round 5
// speedup vs baseline: 1.6141x; 1.6141x over previous
#include <cuda_runtime.h>
#include <cstdint>

#define NPTS 8192
#define KNN  8

typedef unsigned long long u64t;

// packed fp32x2 helpers (FFMA2 path — only reachable via PTX on sm_103a)
__device__ __forceinline__ u64t pk2(float x) {
    u64t r; asm("mov.b64 %0, {%1, %1};" : "=l"(r) : "f"(x)); return r;
}
__device__ __forceinline__ u64t f2fma(u64t a, u64t b, u64t c) {
    u64t d; asm("fma.rn.f32x2 %0, %1, %2, %3;" : "=l"(d) : "l"(a), "l"(b), "l"(c)); return d;
}
__device__ __forceinline__ float2 up2(u64t v) {
    float2 f; asm("mov.b64 {%0, %1}, %2;" : "=f"(f.x), "=f"(f.y) : "l"(v)); return f;
}

// ---------------- scratch (static device globals; no allocation) ----------------
__device__ __align__(16) float4 g_pts4[NPTS];              // x,y,z,|x|^2
__device__ int                  g_idx[NPTS * KNN];         // knn indices (flat)
__device__ __align__(16) float  g_qp1[NPTS * 128];         // [i][0:64]=qA1, [64:128]=pB1
__device__ __align__(16) float  g_x1 [NPTS * 128];         // EdgeConv1 output
__device__ __align__(16) float  g_qp2[NPTS * 256];         // [i][0:128]=qA2, [128:256]=pB2
__device__ __align__(16) float  g_wcat[128 * 256];         // [W3a-W3b | W3b]

// ---------------- prep: pack points + squared norms ----------------
__global__ void k_prep(const float* __restrict__ pc) {
    int i = blockIdx.x * blockDim.x + threadIdx.x;
    if (i < NPTS) {
        float x = pc[3*i], y = pc[3*i+1], z = pc[3*i+2];
        float s = fmaf(x, x, fmaf(y, y, z*z));
        g_pts4[i] = make_float4(x, y, z, s);
    }
}

// ---------------- KNN: block = 64 points x 4 parts, all pts in smem ----------------
__global__ void k_knn() {
    extern __shared__ char sm[];
    float4* sp = (float4*)sm;                                   // 8192 float4 = 128KB
    float*  md = (float*)(sm + NPTS * 16);                      // 64*33 floats
    int*    mi = (int*)  (sm + NPTS * 16 + 64 * 33 * 4);        // 64*33 ints

    int tid = threadIdx.x;
    for (int t = tid; t < NPTS; t += 256) sp[t] = g_pts4[t];
    __syncthreads();

    int part = tid >> 6;             // warp-uniform
    int lp   = tid & 63;
    int pt   = blockIdx.x * 64 + lp;
    float4 me = sp[pt];

    float bd[8]; int bj[8];
#pragma unroll
    for (int s = 0; s < 8; s++) { bd[s] = 3.4e38f; bj[s] = 0x7fffffff; }

    int j0 = part * 2048;
#pragma unroll 4
    for (int jj = 0; jj < 2048; jj++) {
        int j = j0 + jj;
        float4 o = sp[j];
        float dot = fmaf(me.x, o.x, fmaf(me.y, o.y, me.z * o.z));
        float d   = fmaf(-2.0f, dot, me.w + o.w);
        if (d < bd[7]) {                            // strict <: earlier (lower) j wins ties
            bd[7] = d; bj[7] = j;
#pragma unroll
            for (int s = 7; s > 0; s--) {
                if (bd[s] < bd[s-1]) {
                    float td = bd[s]; bd[s] = bd[s-1]; bd[s-1] = td;
                    int   tj = bj[s]; bj[s] = bj[s-1]; bj[s-1] = tj;
                }
            }
        }
    }
#pragma unroll
    for (int s = 0; s < 8; s++) {
        md[lp * 33 + part * 8 + s] = bd[s];
        mi[lp * 33 + part * 8 + s] = bj[s];
    }
    __syncthreads();

    if (tid < 64) {                 // 4-way merge: 8 passes of lex-min over 32
        float* rd = md + tid * 33;
        int*   ri = mi + tid * 33;
        int po = (blockIdx.x * 64 + tid) * KNN;
        for (int s = 0; s < 8; s++) {
            float bdd = 3.4e38f; int bjj = 0x7fffffff; int bp = 0;
            for (int t = 0; t < 32; t++) {
                float dd = rd[t]; int jj = ri[t];
                if (dd < bdd || (dd == bdd && jj < bjj)) { bdd = dd; bjj = jj; bp = t; }
            }
            rd[bp] = 3.4e38f;
            g_idx[po + s] = bjj;
        }
    }
}

// ---------------- P1: x(8192,3) -> qA1 (x@(W1a-W1b)) | pB1 (x@W1b), 64 cols each ----------------
__global__ void k_lin1(const float* __restrict__ W1, const float* __restrict__ pc) {
    int g = blockIdx.x * blockDim.x + threadIdx.x;      // NPTS*32 tasks (float4 each)
    if (g >= NPTS * 32) return;
    int i = g >> 5, q = g & 31;
    float x0 = pc[3*i], x1 = pc[3*i+1], x2 = pc[3*i+2];
    bool isQ = (q < 16);
    int c = (isQ ? q : q - 16) * 4;
    float v[4];
#pragma unroll
    for (int u = 0; u < 4; u++) {
        float wa0 = W1[0*64 + c+u], wa1 = W1[1*64 + c+u], wa2 = W1[2*64 + c+u];
        float wb0 = W1[3*64 + c+u], wb1 = W1[4*64 + c+u], wb2 = W1[5*64 + c+u];
        if (isQ) v[u] = x0*(wa0-wb0) + x1*(wa1-wb1) + x2*(wa2-wb2);
        else     v[u] = x0*wb0 + x1*wb1 + x2*wb2;
    }
    *(float4*)&g_qp1[i * 128 + q * 4] = make_float4(v[0], v[1], v[2], v[3]);
}

// ---------------- build Wcat = [W3a - W3b | W3b]  (128 x 256) ----------------
__global__ void k_wcat(const float* __restrict__ W3) {
    int g = blockIdx.x * blockDim.x + threadIdx.x;      // 128*256
    if (g >= 128 * 256) return;
    int m = g >> 8, n = g & 255;
    float v;
    if (n < 128) v = W3[m * 128 + n] - W3[(m + 128) * 128 + n];
    else         v = W3[(m + 128) * 128 + (n - 128)];
    g_wcat[m * 256 + n] = v;
}

// ---------------- fused GEMM, f32x2 packed, N-tiled ----------------
// Block: 64 rows x 128 cols (N-tile), 256 threads, full-K in smem.
// grid = (rows/64, NOUT/128). nt0 = blockIdx.y*128 selects the W / out column slice.
// EDGE:  A[r][c] = relu(qA[i][c] + pB[idx[r]][c] + bK[c]), i=r/8; epilogue max over 8 k-rows (+bN, opt relu)
// PLAIN: A[r][c] = qA[row][c]; epilogue stores all 64 rows, no bias.
template<int KDIM, int NOUT, bool EDGE, bool RELU_OUT>
__global__ void __launch_bounds__(256) k_gemm(
    const float* __restrict__ qA, const float* __restrict__ pB, int qstride,
    const float* __restrict__ bK, const float* __restrict__ Wg,
    const float* __restrict__ bN, float* __restrict__ out)
{
    extern __shared__ float smf[];
    float* As = smf;                  // [KDIM][64]
    float* Ws = smf + KDIM * 64;      // [KDIM][128]  (this block's N-tile)
    int tid = threadIdx.x;
    int blk = blockIdx.x;
    int nt0 = blockIdx.y * 128;

    // load weight N-tile (row-major slice of Wg[KDIM][NOUT])
    {
        float4*       Ws4 = (float4*)Ws;
        const float4* Wg4 = (const float4*)Wg;
        for (int t = tid; t < KDIM * 32; t += 256) {
            int c = t >> 5, col4 = t & 31;
            Ws4[c * 32 + col4] = Wg4[(c * NOUT + nt0) / 4 + col4];
        }
    }

    // generate A tile (transposed: As[c][rr])
    {
        const int TASKS = 64 * (KDIM / 4);
        int base64 = blk * 64;
        for (int t = tid; t < TASKS; t += 256) {
            int rr = t & 63, c4 = t >> 6;
            float4 v;
            if (EDGE) {
                int i = (base64 + rr) >> 3;
                int j = g_idx[base64 + rr];
                float4 q = *(const float4*)&qA[i * qstride + c4 * 4];
                float4 p = *(const float4*)&pB[(long)j * qstride + c4 * 4];
                float4 b = *(const float4*)&bK[c4 * 4];
                v.x = fmaxf(q.x + p.x + b.x, 0.0f);
                v.y = fmaxf(q.y + p.y + b.y, 0.0f);
                v.z = fmaxf(q.z + p.z + b.z, 0.0f);
                v.w = fmaxf(q.w + p.w + b.w, 0.0f);
            } else {
                v = *(const float4*)&qA[(base64 + rr) * qstride + c4 * 4];
            }
            As[(c4*4 + 0) * 64 + rr] = v.x;
            As[(c4*4 + 1) * 64 + rr] = v.y;
            As[(c4*4 + 2) * 64 + rr] = v.z;
            As[(c4*4 + 3) * 64 + rr] = v.w;
        }
    }
    __syncthreads();

    int tm = tid >> 5;        // warp id -> all lanes share tm => A smem loads broadcast
    int tn = tid & 31;        // lane -> consecutive 16B W loads (conflict-free)

    u64t acc2[8][2];          // 8 k-rows x 4 cols as 2 packed f32x2
#pragma unroll
    for (int kk = 0; kk < 8; kk++) { acc2[kk][0] = 0ull; acc2[kk][1] = 0ull; }

#pragma unroll 2
    for (int c = 0; c < KDIM; c++) {
        float4 a0 = *(const float4*)&As[c * 64 + tm * 8];
        float4 a1 = *(const float4*)&As[c * 64 + tm * 8 + 4];
        float a[8] = {a0.x, a0.y, a0.z, a0.w, a1.x, a1.y, a1.z, a1.w};
        ulonglong2 w = *(const ulonglong2*)&Ws[c * 128 + tn * 4];  // {w0,w1},{w2,w3}
#pragma unroll
        for (int kk = 0; kk < 8; kk++) {
            u64t pa = pk2(a[kk]);              // alu-pipe pack, off the fma pipe
            acc2[kk][0] = f2fma(pa, w.x, acc2[kk][0]);
            acc2[kk][1] = f2fma(pa, w.y, acc2[kk][1]);
        }
    }

    if (EDGE) {
        int pt = blk * 8 + tm;        // one point per warp-row => max is register-local
        float res[4];
#pragma unroll
        for (int h = 0; h < 2; h++) {
            float2 m = up2(acc2[0][h]);
#pragma unroll
            for (int kk = 1; kk < 8; kk++) {
                float2 v = up2(acc2[kk][h]);
                m.x = fmaxf(m.x, v.x);
                m.y = fmaxf(m.y, v.y);
            }
            int n = nt0 + tn * 4 + h * 2;
            m.x += bN[n];     m.y += bN[n + 1];
            if (RELU_OUT) { m.x = fmaxf(m.x, 0.0f); m.y = fmaxf(m.y, 0.0f); }
            res[h*2] = m.x; res[h*2+1] = m.y;
        }
        *(float4*)&out[(long)pt * NOUT + nt0 + tn * 4] =
            make_float4(res[0], res[1], res[2], res[3]);
    } else {
        int base = blk * 64;
#pragma unroll
        for (int kk = 0; kk < 8; kk++) {
            int row = base + tm * 8 + kk;
            float2 lo = up2(acc2[kk][0]);
            float2 hi = up2(acc2[kk][1]);
            *(float4*)&out[(long)row * NOUT + nt0 + tn * 4] =
                make_float4(lo.x, lo.y, hi.x, hi.y);
        }
    }
}

// ---------------- launch ----------------
extern "C" void kernel_launch(void* const* d_in, const int* in_sizes, int n_in,
                              void* d_out, int out_size) {
    const float* pc = (const float*)d_in[0];
    const float* W1 = (const float*)d_in[1];
    const float* b1 = (const float*)d_in[2];
    const float* W2 = (const float*)d_in[3];
    const float* b2 = (const float*)d_in[4];
    const float* W3 = (const float*)d_in[5];
    const float* b3 = (const float*)d_in[6];
    const float* W4 = (const float*)d_in[7];
    const float* b4 = (const float*)d_in[8];
    float* out = (float*)d_out;

    // resolve REAL device addresses of the __device__ scratch symbols
    float *qp1 = nullptr, *x1 = nullptr, *qp2 = nullptr, *wcat = nullptr;
    cudaGetSymbolAddress((void**)&qp1,  g_qp1);
    cudaGetSymbolAddress((void**)&x1,   g_x1);
    cudaGetSymbolAddress((void**)&qp2,  g_qp2);
    cudaGetSymbolAddress((void**)&wcat, g_wcat);

    const int SM_KNN = NPTS * 16 + 2 * 64 * 33 * 4;                 // 147968
    const int SM_EC1 = (64 * 64 + 64 * 128) * 4;                    // 48KB  -> 4 blocks/SM
    const int SM_BIG = (128 * 64 + 128 * 128) * 4;                  // 96KB  -> 2 blocks/SM

    cudaFuncSetAttribute(k_knn, cudaFuncAttributeMaxDynamicSharedMemorySize, SM_KNN);
    cudaFuncSetAttribute((const void*)k_gemm<64,128,true,true>,
                         cudaFuncAttributeMaxDynamicSharedMemorySize, SM_EC1);
    cudaFuncSetAttribute((const void*)k_gemm<128,256,false,false>,
                         cudaFuncAttributeMaxDynamicSharedMemorySize, SM_BIG);
    cudaFuncSetAttribute((const void*)k_gemm<128,256,true,false>,
                         cudaFuncAttributeMaxDynamicSharedMemorySize, SM_BIG);

    // 1. pack points
    k_prep<<<(NPTS + 255) / 256, 256>>>(pc);
    // 2. knn
    k_knn<<<NPTS / 64, 256, SM_KNN>>>();
    // 3. per-point linear factors for EdgeConv1
    k_lin1<<<(NPTS * 32 + 255) / 256, 256>>>(W1, pc);
    // 4. EdgeConv1: edge GEMM (K=64 -> N=128) + max + relu  -> x1
    k_gemm<64,128,true,true><<<dim3(NPTS * KNN / 64, 1), 256, SM_EC1>>>(
        qp1, qp1 + 64, 128, b1, W2, b2, x1);
    // 5. Wcat = [W3a - W3b | W3b]
    k_wcat<<<(128 * 256 + 255) / 256, 256>>>(W3);
    // 6. P2: x1 @ Wcat -> qA2|pB2  (grid.y = 2 N-tiles)
    k_gemm<128,256,false,false><<<dim3(NPTS / 64, 2), 256, SM_BIG>>>(
        x1, nullptr, 128, nullptr, wcat, nullptr, qp2);
    // 7. EdgeConv2: edge GEMM (K=128 -> N=256) + max  -> out  (grid.y = 2 N-tiles)
    k_gemm<128,256,true,false><<<dim3(NPTS * KNN / 64, 2), 256, SM_BIG>>>(
        qp2, qp2 + 128, 256, b3, W4, b4, out);
}